// round 1
// baseline (speedup 1.0000x reference)
#include <cuda_runtime.h>
#include <math.h>

#define N_TOK 4096
#define DMODEL 1024
#define MLP 4096
#define NEXP 8

// ---------------- device scratch (statics: allowed) ----------------
__device__ float g_p[N_TOK];
__device__ int   g_route[N_TOK];
__device__ int   g_cnt[NEXP];
__device__ int   g_off[NEXP + 1];
__device__ int   g_fill[NEXP];
__device__ int   g_perm[N_TOK];
__device__ float g_X[(size_t)N_TOK * DMODEL];        // 16 MB gathered inputs (expert-sorted)
__device__ float g_H[(size_t)N_TOK * MLP];           // 64 MB hidden activations

// ---------------- init ----------------
__global__ void init_kernel() {
    int t = threadIdx.x;
    if (t < NEXP) g_cnt[t] = 0;
}

// ---------------- router: logits -> softmax -> top1 ----------------
__global__ void router_kernel(const float* __restrict__ x,
                              const float* __restrict__ wg,
                              const float* __restrict__ bg) {
    __shared__ float sw[DMODEL * NEXP];   // 32 KB
    int tid = threadIdx.x;                // 128 threads
    for (int i = tid; i < DMODEL * NEXP; i += 128) sw[i] = wg[i];
    __syncthreads();

    int t = blockIdx.x * 128 + tid;       // token id, grid = 32 blocks
    const float* xr = x + (size_t)t * DMODEL;
    float acc[NEXP];
#pragma unroll
    for (int e = 0; e < NEXP; e++) acc[e] = bg[e];
    for (int d = 0; d < DMODEL; d++) {
        float xv = xr[d];
#pragma unroll
        for (int e = 0; e < NEXP; e++) acc[e] += xv * sw[d * NEXP + e];
    }
    float mx = acc[0]; int mi = 0;
#pragma unroll
    for (int e = 1; e < NEXP; e++) if (acc[e] > mx) { mx = acc[e]; mi = e; }
    float s = 0.f;
#pragma unroll
    for (int e = 0; e < NEXP; e++) s += expf(acc[e] - mx);
    g_p[t] = 1.0f / s;     // softmax prob of the argmax
    g_route[t] = mi;
    atomicAdd(&g_cnt[mi], 1);
}

// ---------------- exclusive scan over 8 experts ----------------
__global__ void scan_kernel() {
    if (threadIdx.x == 0) {
        int s = 0;
        for (int e = 0; e < NEXP; e++) { g_off[e] = s; g_fill[e] = s; s += g_cnt[e]; }
        g_off[NEXP] = s;
    }
}

// ---------------- scatter token ids into expert-sorted order ----------------
__global__ void scatter_kernel() {
    int t = blockIdx.x * 256 + threadIdx.x;
    if (t < N_TOK) {
        int e = g_route[t];
        int pos = atomicAdd(&g_fill[e], 1);
        g_perm[pos] = t;
    }
}

// ---------------- gather x rows into g_X (contiguous per expert) ----------------
__global__ void gather_kernel(const float* __restrict__ x) {
    int pos = blockIdx.x;                 // 4096 blocks, 256 threads
    int t = g_perm[pos];
    const float4* src = reinterpret_cast<const float4*>(x + (size_t)t * DMODEL);
    float4* dst = reinterpret_cast<float4*>(g_X + (size_t)pos * DMODEL);
    dst[threadIdx.x] = src[threadIdx.x];  // 256 * 16B = 4 KB row
}

// ---------------- GEMM1: H = relu(Xg @ W1[e] + b1[e]) ----------------
// A: g_X rows [off[e], off[e+1]) lda=1024 ; B: W1[e] 1024x4096 ldb=4096 ; C: g_H ldc=4096
__global__ void gemm1_kernel(const float* __restrict__ W1,
                             const float* __restrict__ b1) {
    const int K = DMODEL, LDB = MLP;
    int e = blockIdx.z;
    int row_end = g_off[e + 1];
    int row0 = g_off[e] + blockIdx.y * 64;
    if (row0 >= row_end) return;
    int mrows = row_end - row0; if (mrows > 64) mrows = 64;
    int n0 = blockIdx.x * 64;

    const float* A = g_X + (size_t)row0 * K;
    const float* B = W1 + (size_t)e * K * LDB + n0;

    __shared__ float As[16][68];   // pad 4 -> 16B aligned rows, fewer conflicts
    __shared__ float Bs[16][64];

    float c[4][4] = {};
    int tid = threadIdx.x;         // 256
    int tx = tid & 15, ty = tid >> 4;
    int ak = tid & 15, am0 = tid >> 4;     // A loader: k fast
    int bn = tid & 63, bk0 = tid >> 6;     // B loader: n fast (coalesced)

    for (int k0 = 0; k0 < K; k0 += 16) {
#pragma unroll
        for (int j = 0; j < 4; j++) {
            int m = am0 + j * 16;
            As[ak][m] = (m < mrows) ? A[(size_t)m * K + k0 + ak] : 0.f;
        }
#pragma unroll
        for (int j = 0; j < 4; j++) {
            int k = bk0 + j * 4;
            Bs[k][bn] = B[(size_t)(k0 + k) * LDB + bn];
        }
        __syncthreads();
#pragma unroll
        for (int k = 0; k < 16; k++) {
            float4 av = *reinterpret_cast<const float4*>(&As[k][ty * 4]);
            float4 bv = *reinterpret_cast<const float4*>(&Bs[k][tx * 4]);
            float aa[4] = {av.x, av.y, av.z, av.w};
            float bb[4] = {bv.x, bv.y, bv.z, bv.w};
#pragma unroll
            for (int i = 0; i < 4; i++)
#pragma unroll
                for (int j = 0; j < 4; j++) c[i][j] += aa[i] * bb[j];
        }
        __syncthreads();
    }

    const float* bias = b1 + (size_t)e * MLP + n0;
#pragma unroll
    for (int i = 0; i < 4; i++) {
        int m = ty * 4 + i;
        if (m < mrows) {
            float* crow = g_H + (size_t)(row0 + m) * MLP + n0;
#pragma unroll
            for (int j = 0; j < 4; j++) {
                int n = tx * 4 + j;
                float v = c[i][j] + bias[n];
                crow[n] = v > 0.f ? v : 0.f;
            }
        }
    }
}

// ---------------- GEMM2: out[tok] = (H @ W2[e] + b2[e]) * p[tok] ----------------
// A: g_H rows [off[e], off[e+1]) lda=4096 ; B: W2[e] 4096x1024 ldb=1024
__global__ void gemm2_kernel(const float* __restrict__ W2,
                             const float* __restrict__ b2,
                             float* __restrict__ out) {
    const int K = MLP, LDB = DMODEL;
    int e = blockIdx.z;
    int row_end = g_off[e + 1];
    int row0 = g_off[e] + blockIdx.y * 64;
    if (row0 >= row_end) return;
    int mrows = row_end - row0; if (mrows > 64) mrows = 64;
    int n0 = blockIdx.x * 64;

    const float* A = g_H + (size_t)row0 * K;
    const float* B = W2 + (size_t)e * K * LDB + n0;

    __shared__ float As[16][68];
    __shared__ float Bs[16][64];

    float c[4][4] = {};
    int tid = threadIdx.x;
    int tx = tid & 15, ty = tid >> 4;
    int ak = tid & 15, am0 = tid >> 4;
    int bn = tid & 63, bk0 = tid >> 6;

    for (int k0 = 0; k0 < K; k0 += 16) {
#pragma unroll
        for (int j = 0; j < 4; j++) {
            int m = am0 + j * 16;
            As[ak][m] = (m < mrows) ? A[(size_t)m * K + k0 + ak] : 0.f;
        }
#pragma unroll
        for (int j = 0; j < 4; j++) {
            int k = bk0 + j * 4;
            Bs[k][bn] = B[(size_t)(k0 + k) * LDB + bn];
        }
        __syncthreads();
#pragma unroll
        for (int k = 0; k < 16; k++) {
            float4 av = *reinterpret_cast<const float4*>(&As[k][ty * 4]);
            float4 bv = *reinterpret_cast<const float4*>(&Bs[k][tx * 4]);
            float aa[4] = {av.x, av.y, av.z, av.w};
            float bb[4] = {bv.x, bv.y, bv.z, bv.w};
#pragma unroll
            for (int i = 0; i < 4; i++)
#pragma unroll
                for (int j = 0; j < 4; j++) c[i][j] += aa[i] * bb[j];
        }
        __syncthreads();
    }

    const float* bias = b2 + (size_t)e * DMODEL + n0;
#pragma unroll
    for (int i = 0; i < 4; i++) {
        int m = ty * 4 + i;
        if (m < mrows) {
            int pos = row0 + m;
            int tok = g_perm[pos];
            float p = g_p[tok];
            float* orow = out + (size_t)tok * DMODEL + n0;
#pragma unroll
            for (int j = 0; j < 4; j++) {
                int n = tx * 4 + j;
                orow[n] = (c[i][j] + bias[n]) * p;
            }
        }
    }
}

// ---------------- launch ----------------
extern "C" void kernel_launch(void* const* d_in, const int* in_sizes, int n_in,
                              void* d_out, int out_size) {
    const float* x   = (const float*)d_in[0];
    const float* wg  = (const float*)d_in[1];
    const float* bg  = (const float*)d_in[2];
    const float* W1  = (const float*)d_in[3];
    const float* b1  = (const float*)d_in[4];
    const float* W2  = (const float*)d_in[5];
    const float* b2  = (const float*)d_in[6];
    float* out = (float*)d_out;

    init_kernel<<<1, 32>>>();
    router_kernel<<<N_TOK / 128, 128>>>(x, wg, bg);
    scan_kernel<<<1, 32>>>();
    scatter_kernel<<<N_TOK / 256, 256>>>();
    gather_kernel<<<N_TOK, 256>>>(x);

    dim3 g1(MLP / 64, N_TOK / 64, NEXP);     // (64, 64, 8)
    gemm1_kernel<<<g1, 256>>>(W1, b1);
    dim3 g2(DMODEL / 64, N_TOK / 64, NEXP);  // (16, 64, 8)
    gemm2_kernel<<<g2, 256>>>(W2, b2, out);
}

// round 2
// speedup vs baseline: 3.1188x; 3.1188x over previous
#include <cuda_runtime.h>
#include <math.h>

#define N_TOK 4096
#define DMODEL 1024
#define MLP 4096
#define NEXP 8

// ---------------- device scratch ----------------
__device__ float g_p[N_TOK];
__device__ int   g_route[N_TOK];
__device__ int   g_cnt[NEXP];
__device__ int   g_off[NEXP + 1];
__device__ int   g_fill[NEXP];
__device__ int   g_perm[N_TOK];
__device__ float g_X[(size_t)N_TOK * DMODEL];        // gathered inputs (expert-sorted)
__device__ float g_H[(size_t)N_TOK * MLP];           // hidden activations

// ---------------- init ----------------
__global__ void init_kernel() {
    int t = threadIdx.x;
    if (t < NEXP) g_cnt[t] = 0;
}

// ---------------- router ----------------
__global__ void router_kernel(const float* __restrict__ x,
                              const float* __restrict__ wg,
                              const float* __restrict__ bg) {
    __shared__ float sw[DMODEL * NEXP];
    int tid = threadIdx.x;
    for (int i = tid; i < DMODEL * NEXP; i += 128) sw[i] = wg[i];
    __syncthreads();

    int t = blockIdx.x * 128 + tid;
    const float* xr = x + (size_t)t * DMODEL;
    float acc[NEXP];
#pragma unroll
    for (int e = 0; e < NEXP; e++) acc[e] = bg[e];
    for (int d = 0; d < DMODEL; d++) {
        float xv = xr[d];
#pragma unroll
        for (int e = 0; e < NEXP; e++) acc[e] += xv * sw[d * NEXP + e];
    }
    float mx = acc[0]; int mi = 0;
#pragma unroll
    for (int e = 1; e < NEXP; e++) if (acc[e] > mx) { mx = acc[e]; mi = e; }
    float s = 0.f;
#pragma unroll
    for (int e = 0; e < NEXP; e++) s += expf(acc[e] - mx);
    g_p[t] = 1.0f / s;
    g_route[t] = mi;
    atomicAdd(&g_cnt[mi], 1);
}

__global__ void scan_kernel() {
    if (threadIdx.x == 0) {
        int s = 0;
        for (int e = 0; e < NEXP; e++) { g_off[e] = s; g_fill[e] = s; s += g_cnt[e]; }
        g_off[NEXP] = s;
    }
}

__global__ void scatter_kernel() {
    int t = blockIdx.x * 256 + threadIdx.x;
    if (t < N_TOK) {
        int e = g_route[t];
        int pos = atomicAdd(&g_fill[e], 1);
        g_perm[pos] = t;
    }
}

__global__ void gather_kernel(const float* __restrict__ x) {
    int pos = blockIdx.x;
    int t = g_perm[pos];
    const float4* src = reinterpret_cast<const float4*>(x + (size_t)t * DMODEL);
    float4* dst = reinterpret_cast<float4*>(g_X + (size_t)pos * DMODEL);
    dst[threadIdx.x] = src[threadIdx.x];
}

// ---------------- tf32 tensor-core grouped GEMM ----------------
// CTA tile 128x128, BK=32, 8 warps (2x4), warp tile 64x32, mma.m16n8k8.tf32.
#define BM 128
#define BN 128
#define BK 32
#define AST 36     // As row stride (floats): banks (4m+k)%32 conflict-free
#define BST 136    // Bs row stride (floats): banks (8k+n)%32 conflict-free
#define ABUF (BM * AST)
#define BBUF (BK * BST)

// RNA-to-tf32 emulation: +half ULP of tf32 before HW's low-13-bit truncation.
__device__ __forceinline__ float rna_tf32(float f) {
    return __uint_as_float(__float_as_uint(f) + 0x1000u);
}

__device__ __forceinline__ void mma_tf32(float c[4], const unsigned a[4], const unsigned b[2]) {
    asm volatile(
        "mma.sync.aligned.m16n8k8.row.col.f32.tf32.tf32.f32 "
        "{%0,%1,%2,%3}, {%4,%5,%6,%7}, {%8,%9}, {%0,%1,%2,%3};\n"
        : "+f"(c[0]), "+f"(c[1]), "+f"(c[2]), "+f"(c[3])
        : "r"(a[0]), "r"(a[1]), "r"(a[2]), "r"(a[3]), "r"(b[0]), "r"(b[1]));
}

// EPI = 1: H = relu(A@B + bias), store to g_H (ldc = N)
// EPI = 2: out[tok] = (A@B + bias) * p[tok], scatter rows via g_perm
template <int EPI>
__global__ __launch_bounds__(256)
void gemm_tc(const float* __restrict__ Bmat, const float* __restrict__ bias_all,
             const float* __restrict__ Asrc, float* __restrict__ Cdst,
             int K, int N) {
    int e = blockIdx.z;
    int row_end = g_off[e + 1];
    int row0 = g_off[e] + blockIdx.y * BM;
    if (row0 >= row_end) return;
    int mrows = min(row_end - row0, BM);
    int n0 = blockIdx.x * BN;

    const float* A = Asrc + (size_t)row0 * K;
    const float* Bg = Bmat + (size_t)e * K * N + n0;

    extern __shared__ float sm[];
    float* sa = sm;                  // 2 * ABUF
    float* sb = sm + 2 * ABUF;       // 2 * BBUF

    int tid = threadIdx.x;
    int warp = tid >> 5, lane = tid & 31;
    int wm = (warp >> 2) * 64;       // warp M offset (2 rows of warps)
    int wn = (warp & 3) * 32;        // warp N offset (4 cols of warps)
    int g = lane >> 2, tig = lane & 3;

    float c[4][4][4];
#pragma unroll
    for (int i = 0; i < 4; i++)
#pragma unroll
        for (int j = 0; j < 4; j++)
#pragma unroll
            for (int r = 0; r < 4; r++) c[i][j][r] = 0.f;

    // loader indexing
    int arow = tid >> 3;             // 0..31, +32*i
    int acol = (tid & 7) * 4;        // 0..28
    int brow = tid >> 5;             // 0..7,  +8*i
    int bcol = (lane) * 4;           // 0..124

    float4 a_st[4], b_st[4];
    const int nch = K / BK;

    // prefetch chunk 0
#pragma unroll
    for (int i = 0; i < 4; i++) {
        int m = arow + 32 * i;
        a_st[i] = (m < mrows) ? *reinterpret_cast<const float4*>(A + (size_t)m * K + acol)
                              : make_float4(0.f, 0.f, 0.f, 0.f);
        b_st[i] = *reinterpret_cast<const float4*>(Bg + (size_t)(brow + 8 * i) * N + bcol);
    }
    {
        float* as = sa; float* bs = sb;
#pragma unroll
        for (int i = 0; i < 4; i++) {
            float4 v = a_st[i];
            v.x = rna_tf32(v.x); v.y = rna_tf32(v.y); v.z = rna_tf32(v.z); v.w = rna_tf32(v.w);
            *reinterpret_cast<float4*>(as + (arow + 32 * i) * AST + acol) = v;
            float4 w = b_st[i];
            w.x = rna_tf32(w.x); w.y = rna_tf32(w.y); w.z = rna_tf32(w.z); w.w = rna_tf32(w.w);
            *reinterpret_cast<float4*>(bs + (brow + 8 * i) * BST + bcol) = w;
        }
    }
    __syncthreads();

    for (int ch = 0; ch < nch; ch++) {
        int buf = ch & 1;
        // prefetch next chunk into registers (overlaps with compute)
        if (ch + 1 < nch) {
            int k0 = (ch + 1) * BK;
#pragma unroll
            for (int i = 0; i < 4; i++) {
                int m = arow + 32 * i;
                a_st[i] = (m < mrows)
                    ? *reinterpret_cast<const float4*>(A + (size_t)m * K + k0 + acol)
                    : make_float4(0.f, 0.f, 0.f, 0.f);
                b_st[i] = *reinterpret_cast<const float4*>(Bg + (size_t)(k0 + brow + 8 * i) * N + bcol);
            }
        }

        // compute on buffer `buf`
        const float* as = sa + buf * ABUF;
        const float* bs = sb + buf * BBUF;
#pragma unroll
        for (int ks = 0; ks < 4; ks++) {
            int kk = ks * 8;
            unsigned af[4][4], bf[4][2];
#pragma unroll
            for (int i = 0; i < 4; i++) {
                int mr = wm + i * 16 + g;
                af[i][0] = __float_as_uint(as[mr * AST + kk + tig]);
                af[i][1] = __float_as_uint(as[(mr + 8) * AST + kk + tig]);
                af[i][2] = __float_as_uint(as[mr * AST + kk + tig + 4]);
                af[i][3] = __float_as_uint(as[(mr + 8) * AST + kk + tig + 4]);
            }
#pragma unroll
            for (int j = 0; j < 4; j++) {
                int nc = wn + j * 8 + g;
                bf[j][0] = __float_as_uint(bs[(kk + tig) * BST + nc]);
                bf[j][1] = __float_as_uint(bs[(kk + tig + 4) * BST + nc]);
            }
#pragma unroll
            for (int i = 0; i < 4; i++)
#pragma unroll
                for (int j = 0; j < 4; j++) mma_tf32(c[i][j], af[i], bf[j]);
        }

        // store next chunk to the other buffer
        if (ch + 1 < nch) {
            float* asn = sa + ((ch + 1) & 1) * ABUF;
            float* bsn = sb + ((ch + 1) & 1) * BBUF;
#pragma unroll
            for (int i = 0; i < 4; i++) {
                float4 v = a_st[i];
                v.x = rna_tf32(v.x); v.y = rna_tf32(v.y); v.z = rna_tf32(v.z); v.w = rna_tf32(v.w);
                *reinterpret_cast<float4*>(asn + (arow + 32 * i) * AST + acol) = v;
                float4 w = b_st[i];
                w.x = rna_tf32(w.x); w.y = rna_tf32(w.y); w.z = rna_tf32(w.z); w.w = rna_tf32(w.w);
                *reinterpret_cast<float4*>(bsn + (brow + 8 * i) * BST + bcol) = w;
            }
        }
        __syncthreads();
    }

    // ---------------- epilogue ----------------
    const float* bias = bias_all + (size_t)e * N + n0;
#pragma unroll
    for (int i = 0; i < 4; i++) {
#pragma unroll
        for (int r2 = 0; r2 < 2; r2++) {
            int mr = wm + i * 16 + g + r2 * 8;
            if (mr >= mrows) continue;
            int grow = row0 + mr;
            if (EPI == 1) {
                float* orow = Cdst + (size_t)grow * N + n0;
#pragma unroll
                for (int j = 0; j < 4; j++) {
                    int nc = wn + j * 8 + 2 * tig;
                    float v0 = c[i][j][2 * r2]     + bias[nc];
                    float v1 = c[i][j][2 * r2 + 1] + bias[nc + 1];
                    float2 o; o.x = v0 > 0.f ? v0 : 0.f; o.y = v1 > 0.f ? v1 : 0.f;
                    *reinterpret_cast<float2*>(orow + nc) = o;
                }
            } else {
                int tok = g_perm[grow];
                float p = g_p[tok];
                float* orow = Cdst + (size_t)tok * N + n0;
#pragma unroll
                for (int j = 0; j < 4; j++) {
                    int nc = wn + j * 8 + 2 * tig;
                    float2 o;
                    o.x = (c[i][j][2 * r2]     + bias[nc])     * p;
                    o.y = (c[i][j][2 * r2 + 1] + bias[nc + 1]) * p;
                    *reinterpret_cast<float2*>(orow + nc) = o;
                }
            }
        }
    }
}

// ---------------- launch ----------------
extern "C" void kernel_launch(void* const* d_in, const int* in_sizes, int n_in,
                              void* d_out, int out_size) {
    const float* x   = (const float*)d_in[0];
    const float* wg  = (const float*)d_in[1];
    const float* bg  = (const float*)d_in[2];
    const float* W1  = (const float*)d_in[3];
    const float* b1  = (const float*)d_in[4];
    const float* W2  = (const float*)d_in[5];
    const float* b2  = (const float*)d_in[6];
    float* out = (float*)d_out;

    const int smem_bytes = (2 * ABUF + 2 * BBUF) * sizeof(float);   // 71680
    cudaFuncSetAttribute(gemm_tc<1>, cudaFuncAttributeMaxDynamicSharedMemorySize, smem_bytes);
    cudaFuncSetAttribute(gemm_tc<2>, cudaFuncAttributeMaxDynamicSharedMemorySize, smem_bytes);

    // resolve device symbol addresses for A/C operands
    float* dX = nullptr; float* dH = nullptr;
    cudaGetSymbolAddress((void**)&dX, g_X);
    cudaGetSymbolAddress((void**)&dH, g_H);

    init_kernel<<<1, 32>>>();
    router_kernel<<<N_TOK / 128, 128>>>(x, wg, bg);
    scan_kernel<<<1, 32>>>();
    scatter_kernel<<<N_TOK / 256, 256>>>();
    gather_kernel<<<N_TOK, 256>>>(x);

    dim3 g1(MLP / BN, N_TOK / BM, NEXP);     // (32, 32, 8)
    gemm_tc<1><<<g1, 256, smem_bytes>>>(W1, b1, dX, dH, DMODEL, MLP);
    dim3 g2(DMODEL / BN, N_TOK / BM, NEXP);  // (8, 32, 8)
    gemm_tc<2><<<g2, 256, smem_bytes>>>(W2, b2, dH, out, MLP, DMODEL);
}

// round 5
// speedup vs baseline: 4.1859x; 1.3421x over previous
#include <cuda_runtime.h>
#include <cuda_fp16.h>
#include <math.h>
#include <stdint.h>

#define N_TOK 4096
#define DMODEL 1024
#define MLP 4096
#define NEXP 8

// ---------------- device scratch ----------------
__device__ float  g_p[N_TOK];
__device__ int    g_route[N_TOK];
__device__ int    g_cnt[NEXP];
__device__ int    g_off[NEXP + 1];
__device__ int    g_fill[NEXP];
__device__ int    g_perm[N_TOK];
__device__ __half g_Xh[(size_t)N_TOK * DMODEL];   // gathered inputs, fp16
__device__ __half g_Hh[(size_t)N_TOK * MLP];      // hidden activations, fp16

// ---------------- small kernels ----------------
__global__ void init_kernel() {
    int t = threadIdx.x;
    if (t < NEXP) g_cnt[t] = 0;
}

__global__ void router_kernel(const float* __restrict__ x,
                              const float* __restrict__ wg,
                              const float* __restrict__ bg) {
    __shared__ float sw[DMODEL * NEXP];
    int tid = threadIdx.x;
    for (int i = tid; i < DMODEL * NEXP; i += 128) sw[i] = wg[i];
    __syncthreads();
    int t = blockIdx.x * 128 + tid;
    const float* xr = x + (size_t)t * DMODEL;
    float acc[NEXP];
#pragma unroll
    for (int e = 0; e < NEXP; e++) acc[e] = bg[e];
    for (int d = 0; d < DMODEL; d++) {
        float xv = xr[d];
#pragma unroll
        for (int e = 0; e < NEXP; e++) acc[e] += xv * sw[d * NEXP + e];
    }
    float mx = acc[0]; int mi = 0;
#pragma unroll
    for (int e = 1; e < NEXP; e++) if (acc[e] > mx) { mx = acc[e]; mi = e; }
    float s = 0.f;
#pragma unroll
    for (int e = 0; e < NEXP; e++) s += expf(acc[e] - mx);
    g_p[t] = 1.0f / s;
    g_route[t] = mi;
    atomicAdd(&g_cnt[mi], 1);
}

__global__ void scan_kernel() {
    if (threadIdx.x == 0) {
        int s = 0;
        for (int e = 0; e < NEXP; e++) { g_off[e] = s; g_fill[e] = s; s += g_cnt[e]; }
        g_off[NEXP] = s;
    }
}

__global__ void scatter_kernel() {
    int t = blockIdx.x * 256 + threadIdx.x;
    if (t < N_TOK) {
        int e = g_route[t];
        int pos = atomicAdd(&g_fill[e], 1);
        g_perm[pos] = t;
    }
}

// gather x rows -> g_Xh (fp16, expert-sorted). 256 thr * 4 elems = 1024/row.
__global__ void gather_kernel(const float* __restrict__ x) {
    int pos = blockIdx.x;
    int t = g_perm[pos];
    const float4* src = reinterpret_cast<const float4*>(x + (size_t)t * DMODEL);
    float4 v = src[threadIdx.x];
    __half2 h0 = __floats2half2_rn(v.x, v.y);
    __half2 h1 = __floats2half2_rn(v.z, v.w);
    uint2 o;
    o.x = *reinterpret_cast<uint32_t*>(&h0);
    o.y = *reinterpret_cast<uint32_t*>(&h1);
    *reinterpret_cast<uint2*>(g_Xh + (size_t)pos * DMODEL + threadIdx.x * 4) = o;
}

// ---------------- fp16 tensor-core grouped GEMM ----------------
// CTA 128x128, BK=32, 8 warps (2x4), warp tile 64x32, mma.m16n8k16.f16 (fp32 acc).
#define BM 128
#define BN 128
#define BK 32
#define AST 40                     // A row stride in halves (80 B)
#define BST 136                    // B row stride in halves (272 B)
#define ABUF_B (BM * AST * 2)      // 10240 B per buffer
#define BBUF_B (BK * BST * 2)      // 8704 B per buffer
#define SMEM_TOT (2 * ABUF_B + 2 * BBUF_B)   // 37888 B

__device__ __forceinline__ uint32_t smem_u32(const void* p) {
    return (uint32_t)__cvta_generic_to_shared(p);
}

__device__ __forceinline__ void ldsm_x4(uint32_t& r0, uint32_t& r1, uint32_t& r2, uint32_t& r3,
                                        uint32_t addr) {
    asm volatile("ldmatrix.sync.aligned.m8n8.x4.shared.b16 {%0,%1,%2,%3}, [%4];"
                 : "=r"(r0), "=r"(r1), "=r"(r2), "=r"(r3) : "r"(addr));
}
__device__ __forceinline__ void ldsm_x4_t(uint32_t& r0, uint32_t& r1, uint32_t& r2, uint32_t& r3,
                                          uint32_t addr) {
    asm volatile("ldmatrix.sync.aligned.m8n8.x4.trans.shared.b16 {%0,%1,%2,%3}, [%4];"
                 : "=r"(r0), "=r"(r1), "=r"(r2), "=r"(r3) : "r"(addr));
}
__device__ __forceinline__ void mma_fp16(float c[4], const uint32_t a[4], const uint32_t b[2]) {
    asm volatile(
        "mma.sync.aligned.m16n8k16.row.col.f32.f16.f16.f32 "
        "{%0,%1,%2,%3}, {%4,%5,%6,%7}, {%8,%9}, {%0,%1,%2,%3};\n"
        : "+f"(c[0]), "+f"(c[1]), "+f"(c[2]), "+f"(c[3])
        : "r"(a[0]), "r"(a[1]), "r"(a[2]), "r"(a[3]), "r"(b[0]), "r"(b[1]));
}

// EPI = 1: Cdst = g_Hh (half), relu(A@B + bias)
// EPI = 2: Cdst = out (float), (A@B + bias) * p[tok], row-scattered
template <int EPI>
__global__ __launch_bounds__(256)
void gemm_fp16(const float* __restrict__ Bmat, const float* __restrict__ bias_all,
               const __half* __restrict__ Asrc, void* __restrict__ Cdst,
               int K, int N) {
    int e = blockIdx.z;
    int row_end = g_off[e + 1];
    int row0 = g_off[e] + blockIdx.y * BM;
    if (row0 >= row_end) return;
    int mrows = min(row_end - row0, BM);
    int n0 = blockIdx.x * BN;

    const __half* A = Asrc + (size_t)row0 * K;
    const float* Bg = Bmat + (size_t)e * K * N + n0;

    __shared__ char smem[SMEM_TOT];
    char* sa = smem;                 // A buffers
    char* sb = smem + 2 * ABUF_B;    // B buffers
    uint32_t sa32 = smem_u32(sa);
    uint32_t sb32 = smem_u32(sb);

    int tid = threadIdx.x;
    int warp = tid >> 5, lane = tid & 31;
    int wm = (warp >> 2) * 64;       // warp M offset
    int wn = (warp & 3) * 32;        // warp N offset
    int g = lane >> 2, tig = lane & 3;

    float c[4][4][4];
#pragma unroll
    for (int i = 0; i < 4; i++)
#pragma unroll
        for (int j = 0; j < 4; j++)
#pragma unroll
            for (int r = 0; r < 4; r++) c[i][j][r] = 0.f;

    // ldmatrix per-lane address components (bytes)
    uint32_t a_lane_off = (uint32_t)((wm + (lane & 15)) * (AST * 2) + (lane >> 4) * 16);
    uint32_t b_lane_off = (uint32_t)(((lane & 7) + ((lane >> 3) & 1) * 8) * (BST * 2)
                                     + (wn + (lane >> 4) * 8) * 2);

    // loader indexing
    // A: 512 16B-chunks (128 rows x 4); thread handles chunks tid and tid+256.
    int am0 = tid >> 2, ak0 = (tid & 3) * 8;           // chunk tid
    int am1 = (tid + 256) >> 2, ak1 = ak0;             // chunk tid+256 (same k column)
    // B: thread t: k = t>>3, n0b = (t&7)*16 ; 4 float4 -> 16 halves
    int bk = tid >> 3, bn = (tid & 7) * 16;

    uint4  a_st[2];
    float4 b_st[4];

    const int nch = K / BK;

    // ---- prefetch + store chunk 0 ----
    a_st[0] = (am0 < mrows) ? *reinterpret_cast<const uint4*>(A + (size_t)am0 * K + ak0)
                            : make_uint4(0, 0, 0, 0);
    a_st[1] = (am1 < mrows) ? *reinterpret_cast<const uint4*>(A + (size_t)am1 * K + ak1)
                            : make_uint4(0, 0, 0, 0);
#pragma unroll
    for (int q = 0; q < 4; q++)
        b_st[q] = *reinterpret_cast<const float4*>(Bg + (size_t)bk * N + bn + q * 4);

    {
        *reinterpret_cast<uint4*>(sa + am0 * (AST * 2) + ak0 * 2) = a_st[0];
        *reinterpret_cast<uint4*>(sa + am1 * (AST * 2) + ak1 * 2) = a_st[1];
        __half2 h[8];
#pragma unroll
        for (int q = 0; q < 4; q++) {
            h[q * 2]     = __floats2half2_rn(b_st[q].x, b_st[q].y);
            h[q * 2 + 1] = __floats2half2_rn(b_st[q].z, b_st[q].w);
        }
        *reinterpret_cast<uint4*>(sb + bk * (BST * 2) + bn * 2)      = *reinterpret_cast<uint4*>(&h[0]);
        *reinterpret_cast<uint4*>(sb + bk * (BST * 2) + bn * 2 + 16) = *reinterpret_cast<uint4*>(&h[4]);
    }
    __syncthreads();

    for (int ch = 0; ch < nch; ch++) {
        int buf = ch & 1;

        // prefetch next chunk (global -> regs)
        if (ch + 1 < nch) {
            int k0 = (ch + 1) * BK;
            a_st[0] = (am0 < mrows) ? *reinterpret_cast<const uint4*>(A + (size_t)am0 * K + k0 + ak0)
                                    : make_uint4(0, 0, 0, 0);
            a_st[1] = (am1 < mrows) ? *reinterpret_cast<const uint4*>(A + (size_t)am1 * K + k0 + ak1)
                                    : make_uint4(0, 0, 0, 0);
#pragma unroll
            for (int q = 0; q < 4; q++)
                b_st[q] = *reinterpret_cast<const float4*>(Bg + (size_t)(k0 + bk) * N + bn + q * 4);
        }

        // compute on buffer `buf`
        uint32_t abase = sa32 + buf * ABUF_B + a_lane_off;
        uint32_t bbase = sb32 + buf * BBUF_B + b_lane_off;
#pragma unroll
        for (int ks = 0; ks < 2; ks++) {
            int kk = ks * 16;
            uint32_t af[4][4], bf[4][2];
#pragma unroll
            for (int i = 0; i < 4; i++)
                ldsm_x4(af[i][0], af[i][1], af[i][2], af[i][3],
                        abase + (uint32_t)(i * 16 * (AST * 2) + kk * 2));
#pragma unroll
            for (int jp = 0; jp < 2; jp++)
                ldsm_x4_t(bf[2 * jp][0], bf[2 * jp][1], bf[2 * jp + 1][0], bf[2 * jp + 1][1],
                          bbase + (uint32_t)(kk * (BST * 2) + jp * 32));
#pragma unroll
            for (int i = 0; i < 4; i++)
#pragma unroll
                for (int j = 0; j < 4; j++) mma_fp16(c[i][j], af[i], bf[j]);
        }

        // store next chunk to the other buffer
        if (ch + 1 < nch) {
            char* san = sa + ((ch + 1) & 1) * ABUF_B;
            char* sbn = sb + ((ch + 1) & 1) * BBUF_B;
            *reinterpret_cast<uint4*>(san + am0 * (AST * 2) + ak0 * 2) = a_st[0];
            *reinterpret_cast<uint4*>(san + am1 * (AST * 2) + ak1 * 2) = a_st[1];
            __half2 h[8];
#pragma unroll
            for (int q = 0; q < 4; q++) {
                h[q * 2]     = __floats2half2_rn(b_st[q].x, b_st[q].y);
                h[q * 2 + 1] = __floats2half2_rn(b_st[q].z, b_st[q].w);
            }
            *reinterpret_cast<uint4*>(sbn + bk * (BST * 2) + bn * 2)      = *reinterpret_cast<uint4*>(&h[0]);
            *reinterpret_cast<uint4*>(sbn + bk * (BST * 2) + bn * 2 + 16) = *reinterpret_cast<uint4*>(&h[4]);
        }
        __syncthreads();
    }

    // ---------------- epilogue ----------------
    const float* bias = bias_all + (size_t)e * N + n0;
#pragma unroll
    for (int i = 0; i < 4; i++) {
#pragma unroll
        for (int r2 = 0; r2 < 2; r2++) {
            int mr = wm + i * 16 + g + r2 * 8;
            if (mr >= mrows) continue;
            int grow = row0 + mr;
            if (EPI == 1) {
                __half* orow = (__half*)Cdst + (size_t)grow * N + n0;
#pragma unroll
                for (int j = 0; j < 4; j++) {
                    int nc = wn + j * 8 + 2 * tig;
                    float v0 = c[i][j][2 * r2]     + bias[nc];
                    float v1 = c[i][j][2 * r2 + 1] + bias[nc + 1];
                    v0 = v0 > 0.f ? v0 : 0.f;
                    v1 = v1 > 0.f ? v1 : 0.f;
                    __half2 h = __floats2half2_rn(v0, v1);
                    *reinterpret_cast<__half2*>(orow + nc) = h;
                }
            } else {
                int tok = g_perm[grow];
                float p = g_p[tok];
                float* orow = (float*)Cdst + (size_t)tok * N + n0;
#pragma unroll
                for (int j = 0; j < 4; j++) {
                    int nc = wn + j * 8 + 2 * tig;
                    float2 o;
                    o.x = (c[i][j][2 * r2]     + bias[nc])     * p;
                    o.y = (c[i][j][2 * r2 + 1] + bias[nc + 1]) * p;
                    *reinterpret_cast<float2*>(orow + nc) = o;
                }
            }
        }
    }
}

// ---------------- launch ----------------
extern "C" void kernel_launch(void* const* d_in, const int* in_sizes, int n_in,
                              void* d_out, int out_size) {
    const float* x   = (const float*)d_in[0];
    const float* wg  = (const float*)d_in[1];
    const float* bg  = (const float*)d_in[2];
    const float* W1  = (const float*)d_in[3];
    const float* b1  = (const float*)d_in[4];
    const float* W2  = (const float*)d_in[5];
    const float* b2  = (const float*)d_in[6];
    float* out = (float*)d_out;

    __half* dX = nullptr; __half* dH = nullptr;
    cudaGetSymbolAddress((void**)&dX, g_Xh);
    cudaGetSymbolAddress((void**)&dH, g_Hh);

    init_kernel<<<1, 32>>>();
    router_kernel<<<N_TOK / 128, 128>>>(x, wg, bg);
    scan_kernel<<<1, 32>>>();
    scatter_kernel<<<N_TOK / 256, 256>>>();
    gather_kernel<<<N_TOK, 256>>>(x);

    dim3 g1(MLP / BN, N_TOK / BM, NEXP);     // (32, 32, 8)
    gemm_fp16<1><<<g1, 256>>>(W1, b1, dX, (void*)dH, DMODEL, MLP);
    dim3 g2(DMODEL / BN, N_TOK / BM, NEXP);  // (8, 32, 8)
    gemm_fp16<2><<<g2, 256>>>(W2, b2, dH, (void*)out, MLP, DMODEL);
}